// round 1
// baseline (speedup 1.0000x reference)
#include <cuda_runtime.h>

#define Bn 8
#define Cn 64
#define Hn 64
#define Wn 64
#define CTXn 64
#define CH2 32

// Intermediates (no cudaMalloc allowed)
__device__ float g_f1[Bn*CTXn*Hn*Wn];          // conv1 output, [b][c][h][w]
__device__ float g_f2t[Bn*CH2*Wn*Hn];          // conv2 output TRANSPOSED: [b][c][w][h]

// ---------------------------------------------------------------------------
// conv1: 3x3, Cin=64, Cout=64, zero pad=1, +bias, PReLU.  block=(h,b), 256 thr
// thread: 4 co x 4 w register tile; ci processed in chunks of 8 via smem.
// ---------------------------------------------------------------------------
__global__ __launch_bounds__(256) void conv1_kernel(
    const float* __restrict__ x, const float* __restrict__ wgt,
    const float* __restrict__ bias, const float* __restrict__ alpha)
{
    const int h = blockIdx.x, b = blockIdx.y;
    const int tid = threadIdx.x;
    const int w_base  = (tid & 15) * 4;
    const int co_base = (tid >> 4) * 4;

    __shared__ float sin_[8][3][66];
    __shared__ float sw[64][8][9];

    float acc[4][4];
#pragma unroll
    for (int i = 0; i < 4; i++)
#pragma unroll
        for (int j = 0; j < 4; j++) acc[i][j] = 0.f;

    for (int cb = 0; cb < 8; cb++) {
        for (int idx = tid; idx < 8*3*66; idx += 256) {
            int ci_l = idx / 198;
            int r    = (idx % 198) / 66;
            int cc   = idx % 66;
            int hh = h - 1 + r;
            int ww = cc - 1;
            float v = 0.f;
            if (hh >= 0 && hh < Hn && ww >= 0 && ww < Wn)
                v = x[((b*CTXn + cb*8 + ci_l)*Hn + hh)*Wn + ww];
            sin_[ci_l][r][cc] = v;
        }
        for (int idx = tid; idx < 64*8*9; idx += 256) {
            int co   = idx / 72;
            int ci_l = (idx % 72) / 9;
            int kk   = idx % 9;
            sw[co][ci_l][kk] = wgt[(co*CTXn + cb*8 + ci_l)*9 + kk];
        }
        __syncthreads();

#pragma unroll
        for (int ci_l = 0; ci_l < 8; ci_l++) {
            float iv[3][6];
#pragma unroll
            for (int r = 0; r < 3; r++)
#pragma unroll
                for (int u = 0; u < 6; u++) iv[r][u] = sin_[ci_l][r][w_base + u];
#pragma unroll
            for (int cl = 0; cl < 4; cl++) {
                float wt[9];
#pragma unroll
                for (int kk = 0; kk < 9; kk++) wt[kk] = sw[co_base + cl][ci_l][kk];
#pragma unroll
                for (int ky = 0; ky < 3; ky++)
#pragma unroll
                    for (int kx = 0; kx < 3; kx++)
#pragma unroll
                        for (int wo = 0; wo < 4; wo++)
                            acc[cl][wo] = fmaf(wt[ky*3+kx], iv[ky][wo+kx], acc[cl][wo]);
            }
        }
        __syncthreads();
    }

#pragma unroll
    for (int cl = 0; cl < 4; cl++) {
        int co = co_base + cl;
        float bv = bias[co], av = alpha[co];
#pragma unroll
        for (int wo = 0; wo < 4; wo++) {
            float v = acc[cl][wo] + bv;
            v = v > 0.f ? v : av * v;
            g_f1[((b*CTXn + co)*Hn + h)*Wn + w_base + wo] = v;
        }
    }
}

// ---------------------------------------------------------------------------
// conv2: 3x3, Cin=64, Cout=32, zero pad=1, +bias, PReLU.
// Writes output TRANSPOSED as [b][co][w][h] so the fused kernel loads coalesced.
// ---------------------------------------------------------------------------
__global__ __launch_bounds__(256) void conv2_kernel(
    const float* __restrict__ wgt, const float* __restrict__ bias,
    const float* __restrict__ alpha)
{
    const int h = blockIdx.x, b = blockIdx.y;
    const int tid = threadIdx.x;
    const int w_base  = (tid & 15) * 4;
    const int co_base = (tid >> 4) * 2;

    __shared__ float sin_[8][3][66];
    __shared__ float sw[32][8][9];

    float acc[2][4];
#pragma unroll
    for (int i = 0; i < 2; i++)
#pragma unroll
        for (int j = 0; j < 4; j++) acc[i][j] = 0.f;

    for (int cb = 0; cb < 8; cb++) {
        for (int idx = tid; idx < 8*3*66; idx += 256) {
            int ci_l = idx / 198;
            int r    = (idx % 198) / 66;
            int cc   = idx % 66;
            int hh = h - 1 + r;
            int ww = cc - 1;
            float v = 0.f;
            if (hh >= 0 && hh < Hn && ww >= 0 && ww < Wn)
                v = g_f1[((b*CTXn + cb*8 + ci_l)*Hn + hh)*Wn + ww];
            sin_[ci_l][r][cc] = v;
        }
        for (int idx = tid; idx < 32*8*9; idx += 256) {
            int co   = idx / 72;
            int ci_l = (idx % 72) / 9;
            int kk   = idx % 9;
            sw[co][ci_l][kk] = wgt[(co*CTXn + cb*8 + ci_l)*9 + kk];
        }
        __syncthreads();

#pragma unroll
        for (int ci_l = 0; ci_l < 8; ci_l++) {
            float iv[3][6];
#pragma unroll
            for (int r = 0; r < 3; r++)
#pragma unroll
                for (int u = 0; u < 6; u++) iv[r][u] = sin_[ci_l][r][w_base + u];
#pragma unroll
            for (int cl = 0; cl < 2; cl++) {
                float wt[9];
#pragma unroll
                for (int kk = 0; kk < 9; kk++) wt[kk] = sw[co_base + cl][ci_l][kk];
#pragma unroll
                for (int ky = 0; ky < 3; ky++)
#pragma unroll
                    for (int kx = 0; kx < 3; kx++)
#pragma unroll
                        for (int wo = 0; wo < 4; wo++)
                            acc[cl][wo] = fmaf(wt[ky*3+kx], iv[ky][wo+kx], acc[cl][wo]);
            }
        }
        __syncthreads();
    }

#pragma unroll
    for (int cl = 0; cl < 2; cl++) {
        int co = co_base + cl;
        float bv = bias[co], av = alpha[co];
#pragma unroll
        for (int wo = 0; wo < 4; wo++) {
            float v = acc[cl][wo] + bv;
            v = v > 0.f ? v : av * v;
            g_f2t[((b*CH2 + co)*Wn + (w_base + wo))*Hn + h] = v;   // transposed
        }
    }
}

// ---------------------------------------------------------------------------
// Fused: 1x1 conv (GEMM 2304x(H*W), K=32) + softmax over 9 + upsample.
// Block = (c_chunk of 4 channels, w, b). Pixels tiled along h (full 64 row).
// Thread = (c_l in 4, pq in 4, pg in 16): owns 9 k-logits x 4 h-pixels
// -> softmax entirely in registers, mask never hits memory.
// Reference quirk: out[b][c][2w+q][2h+p]  (transpose(0,1,5,3,4,2)).
// ---------------------------------------------------------------------------
__global__ __launch_bounds__(256, 3) void fused_kernel(
    const float* __restrict__ xlow, const float* __restrict__ kw,
    const float* __restrict__ kb, float* __restrict__ out)
{
    const int cchunk = blockIdx.x;   // 0..15 -> 4 channels each
    const int w      = blockIdx.y;   // 0..63
    const int b      = blockIdx.z;
    const int tid = threadIdx.x;
    const int pg  = tid & 15;        // pixel group: h = pg*4 + j
    const int pq  = (tid >> 4) & 3;
    const int c_l = tid >> 6;        // 0..3

    __shared__ float swt[144*33];                 // weights, padded stride 33
    __shared__ __align__(16) float sf2[32*64];    // [ci][h]
    __shared__ float sx[4][3][66];                // [c_l][dx][h+1], edge-clamped
    __shared__ float sbias[144];

    // f2 tile (coalesced thanks to transposed layout)
    for (int idx = tid; idx < 32*64; idx += 256)
        sf2[idx] = g_f2t[((b*CH2 + (idx >> 6))*Wn + w)*Hn + (idx & 63)];
    // weight chunk: rows cchunk*144 .. +143
    for (int idx = tid; idx < 144*32; idx += 256) {
        int r = idx >> 5, ci = idx & 31;
        swt[r*33 + ci] = kw[(cchunk*144 + r)*32 + ci];
    }
    if (tid < 144) sbias[tid] = kb[cchunk*144 + tid];
    // x_low 3-column patch, EDGE clamped both dims
    for (int idx = tid; idx < 4*3*66; idx += 256) {
        int cl = idx / 198;
        int dx = (idx % 198) / 66;
        int hh = idx % 66;
        int hr = min(max(hh - 1, 0), Hn - 1);
        int wc = min(max(w + dx - 1, 0), Wn - 1);
        sx[cl][dx][hh] = xlow[((b*Cn + cchunk*4 + cl)*Hn + hr)*Wn + wc];
    }
    __syncthreads();

    float m[9][4];
#pragma unroll
    for (int k = 0; k < 9; k++)
#pragma unroll
        for (int j = 0; j < 4; j++) m[k][j] = 0.f;

    const int rowbase = c_l*36 + pq;     // mask row for k=0: c*36 + k*4 + pq
#pragma unroll 4
    for (int ci = 0; ci < 32; ci++) {
        float4 bf = *(const float4*)(&sf2[ci*64 + pg*4]);
#pragma unroll
        for (int k = 0; k < 9; k++) {
            float a = swt[(rowbase + k*4)*33 + ci];
            m[k][0] = fmaf(a, bf.x, m[k][0]);
            m[k][1] = fmaf(a, bf.y, m[k][1]);
            m[k][2] = fmaf(a, bf.z, m[k][2]);
            m[k][3] = fmaf(a, bf.w, m[k][3]);
        }
    }

    float b9[9];
#pragma unroll
    for (int k = 0; k < 9; k++) b9[k] = sbias[rowbase + k*4];

    const int c = cchunk*4 + c_l;
    const int p = pq >> 1, q = pq & 1;
#pragma unroll
    for (int j = 0; j < 4; j++) {
        const int hpix = pg*4 + j;
        float lg[9];
        float mx = -1e30f;
#pragma unroll
        for (int k = 0; k < 9; k++) { lg[k] = m[k][j] + b9[k]; mx = fmaxf(mx, lg[k]); }
        float se = 0.f, sv = 0.f;
#pragma unroll
        for (int k = 0; k < 9; k++) {
            float e = __expf(lg[k] - mx);
            se += e;
            float nb = sx[c_l][k % 3][hpix + (k / 3)];   // x[clamp(h+dy-1)][clamp(w+dx-1)]
            sv = fmaf(e, nb, sv);
        }
        float val = sv / se;
        // reference transpose(0,1,5,3,4,2): out[b][c][2w+q][2h+p]
        out[((b*Cn + c)*128 + (2*w + q))*128 + (2*hpix + p)] = val;
    }
}

extern "C" void kernel_launch(void* const* d_in, const int* in_sizes, int n_in,
                              void* d_out, int out_size)
{
    const float* x_low = (const float*)d_in[0];
    const float* ctx   = (const float*)d_in[1];
    const float* c1_w  = (const float*)d_in[2];
    const float* c1_b  = (const float*)d_in[3];
    const float* p1_a  = (const float*)d_in[4];
    const float* c2_w  = (const float*)d_in[5];
    const float* c2_b  = (const float*)d_in[6];
    const float* p2_a  = (const float*)d_in[7];
    const float* kp_w  = (const float*)d_in[8];
    const float* kp_b  = (const float*)d_in[9];
    float* out = (float*)d_out;

    conv1_kernel<<<dim3(Hn, Bn), 256>>>(ctx, c1_w, c1_b, p1_a);
    conv2_kernel<<<dim3(Hn, Bn), 256>>>(c2_w, c2_b, p2_a);
    fused_kernel<<<dim3(16, Wn, Bn), 256>>>(x_low, kp_w, kp_b, out);
}

// round 2
// speedup vs baseline: 1.0859x; 1.0859x over previous
#include <cuda_runtime.h>

#define Bn 8
#define Cn 64
#define Hn 64
#define Wn 64
#define CTXn 64
#define CH2 32

typedef unsigned long long ull;

__device__ __forceinline__ ull pack2(float lo, float hi) {
    ull r; asm("mov.b64 %0, {%1, %2};" : "=l"(r) : "f"(lo), "f"(hi)); return r;
}
__device__ __forceinline__ void unpack2(ull v, float& lo, float& hi) {
    asm("mov.b64 {%0, %1}, %2;" : "=f"(lo), "=f"(hi) : "l"(v));
}
__device__ __forceinline__ ull ffma2(ull a, ull b, ull c) {
    ull d; asm("fma.rn.f32x2 %0, %1, %2, %3;" : "=l"(d) : "l"(a), "l"(b), "l"(c)); return d;
}

// Intermediates (no cudaMalloc allowed)
__device__ float g_f1[Bn*CTXn*Hn*Wn];          // conv1 output, [b][c][h][w]
__device__ float g_f2t[Bn*CH2*Wn*Hn];          // conv2 output TRANSPOSED: [b][c][w][h]

// ---------------------------------------------------------------------------
// conv1: 3x3, 64->64, zero pad, bias+PReLU.
// Block covers 2 h rows. Thread: 4 co x 8 w (4 f32x2 pairs). 256 threads.
// ---------------------------------------------------------------------------
__global__ __launch_bounds__(256) void conv1_kernel(
    const float* __restrict__ x, const float* __restrict__ wgt,
    const float* __restrict__ bias, const float* __restrict__ alpha)
{
    const int h0 = blockIdx.x * 2, b = blockIdx.y;
    const int tid = threadIdx.x;
    const int row = tid >> 7;           // 0..1
    const int t2  = tid & 127;
    const int w_base  = (t2 & 7) * 8;   // 8 pixels
    const int co_base = (t2 >> 3) * 4;  // 4 channels

    __shared__ __align__(16) float sin_[8][4][68];   // [ci][r][col], col=w+1
    __shared__ ull swd[64][8][9];                    // duplicated weights

    ull A[4][4];
#pragma unroll
    for (int i = 0; i < 4; i++)
#pragma unroll
        for (int j = 0; j < 4; j++) A[i][j] = 0ull;

    for (int cb = 0; cb < 8; cb++) {
        for (int idx = tid; idx < 8*4*66; idx += 256) {
            int ci_l = idx / 264;
            int rem  = idx % 264;
            int r    = rem / 66;
            int cc   = rem % 66;
            int hh = h0 - 1 + r, ww = cc - 1;
            float v = 0.f;
            if (hh >= 0 && hh < Hn && ww >= 0 && ww < Wn)
                v = x[((b*CTXn + cb*8 + ci_l)*Hn + hh)*Wn + ww];
            sin_[ci_l][r][cc] = v;
        }
        for (int idx = tid; idx < 64*8*9; idx += 256) {
            int co   = idx / 72;
            int ci_l = (idx % 72) / 9;
            int kk   = idx % 9;
            float v = wgt[(co*CTXn + cb*8 + ci_l)*9 + kk];
            swd[co][ci_l][kk] = pack2(v, v);
        }
        __syncthreads();

#pragma unroll
        for (int ci_l = 0; ci_l < 8; ci_l++) {
#pragma unroll
            for (int ky = 0; ky < 3; ky++) {
                const float* bp = &sin_[ci_l][row + ky][w_base];
                float4 fa = *(const float4*)bp;
                float4 fb = *(const float4*)(bp + 4);
                float2 fc = *(const float2*)(bp + 8);
                float v0=fa.x,v1=fa.y,v2=fa.z,v3=fa.w,v4=fb.x,v5=fb.y,v6=fb.z,v7=fb.w,v8=fc.x,v9=fc.y;
                ull P[9];
                P[0]=pack2(v0,v1); P[1]=pack2(v1,v2); P[2]=pack2(v2,v3);
                P[3]=pack2(v3,v4); P[4]=pack2(v4,v5); P[5]=pack2(v5,v6);
                P[6]=pack2(v6,v7); P[7]=pack2(v7,v8); P[8]=pack2(v8,v9);
#pragma unroll
                for (int cl = 0; cl < 4; cl++) {
                    ull w0 = swd[co_base+cl][ci_l][ky*3+0];
                    ull w1 = swd[co_base+cl][ci_l][ky*3+1];
                    ull w2 = swd[co_base+cl][ci_l][ky*3+2];
#pragma unroll
                    for (int j = 0; j < 4; j++) {
                        A[cl][j] = ffma2(w0, P[2*j+0], A[cl][j]);
                        A[cl][j] = ffma2(w1, P[2*j+1], A[cl][j]);
                        A[cl][j] = ffma2(w2, P[2*j+2], A[cl][j]);
                    }
                }
            }
        }
        __syncthreads();
    }

    const int h = h0 + row;
#pragma unroll
    for (int cl = 0; cl < 4; cl++) {
        int co = co_base + cl;
        float bv = bias[co], av = alpha[co];
        float* op = &g_f1[((b*CTXn + co)*Hn + h)*Wn + w_base];
#pragma unroll
        for (int j = 0; j < 4; j++) {
            float lo, hi; unpack2(A[cl][j], lo, hi);
            lo += bv; hi += bv;
            lo = lo > 0.f ? lo : av * lo;
            hi = hi > 0.f ? hi : av * hi;
            op[2*j]   = lo;
            op[2*j+1] = hi;
        }
    }
}

// ---------------------------------------------------------------------------
// conv2: 3x3, 64->32, zero pad, bias+PReLU. Output transposed [b][c][w][h].
// Block covers 2 h rows. Thread: 2 co x 8 w. 256 threads.
// ---------------------------------------------------------------------------
__global__ __launch_bounds__(256) void conv2_kernel(
    const float* __restrict__ wgt, const float* __restrict__ bias,
    const float* __restrict__ alpha)
{
    const int h0 = blockIdx.x * 2, b = blockIdx.y;
    const int tid = threadIdx.x;
    const int row = tid >> 7;
    const int t2  = tid & 127;
    const int w_base  = (t2 & 7) * 8;
    const int co_base = (t2 >> 3) * 2;

    __shared__ __align__(16) float sin_[8][4][68];
    __shared__ ull swd[32][8][9];

    ull A[2][4];
#pragma unroll
    for (int i = 0; i < 2; i++)
#pragma unroll
        for (int j = 0; j < 4; j++) A[i][j] = 0ull;

    for (int cb = 0; cb < 8; cb++) {
        for (int idx = tid; idx < 8*4*66; idx += 256) {
            int ci_l = idx / 264;
            int rem  = idx % 264;
            int r    = rem / 66;
            int cc   = rem % 66;
            int hh = h0 - 1 + r, ww = cc - 1;
            float v = 0.f;
            if (hh >= 0 && hh < Hn && ww >= 0 && ww < Wn)
                v = g_f1[((b*CTXn + cb*8 + ci_l)*Hn + hh)*Wn + ww];
            sin_[ci_l][r][cc] = v;
        }
        for (int idx = tid; idx < 32*8*9; idx += 256) {
            int co   = idx / 72;
            int ci_l = (idx % 72) / 9;
            int kk   = idx % 9;
            float v = wgt[(co*CTXn + cb*8 + ci_l)*9 + kk];
            swd[co][ci_l][kk] = pack2(v, v);
        }
        __syncthreads();

#pragma unroll
        for (int ci_l = 0; ci_l < 8; ci_l++) {
#pragma unroll
            for (int ky = 0; ky < 3; ky++) {
                const float* bp = &sin_[ci_l][row + ky][w_base];
                float4 fa = *(const float4*)bp;
                float4 fb = *(const float4*)(bp + 4);
                float2 fc = *(const float2*)(bp + 8);
                float v0=fa.x,v1=fa.y,v2=fa.z,v3=fa.w,v4=fb.x,v5=fb.y,v6=fb.z,v7=fb.w,v8=fc.x,v9=fc.y;
                ull P[9];
                P[0]=pack2(v0,v1); P[1]=pack2(v1,v2); P[2]=pack2(v2,v3);
                P[3]=pack2(v3,v4); P[4]=pack2(v4,v5); P[5]=pack2(v5,v6);
                P[6]=pack2(v6,v7); P[7]=pack2(v7,v8); P[8]=pack2(v8,v9);
#pragma unroll
                for (int cl = 0; cl < 2; cl++) {
                    ull w0 = swd[co_base+cl][ci_l][ky*3+0];
                    ull w1 = swd[co_base+cl][ci_l][ky*3+1];
                    ull w2 = swd[co_base+cl][ci_l][ky*3+2];
#pragma unroll
                    for (int j = 0; j < 4; j++) {
                        A[cl][j] = ffma2(w0, P[2*j+0], A[cl][j]);
                        A[cl][j] = ffma2(w1, P[2*j+1], A[cl][j]);
                        A[cl][j] = ffma2(w2, P[2*j+2], A[cl][j]);
                    }
                }
            }
        }
        __syncthreads();
    }

    const int h = h0 + row;
#pragma unroll
    for (int cl = 0; cl < 2; cl++) {
        int co = co_base + cl;
        float bv = bias[co], av = alpha[co];
#pragma unroll
        for (int j = 0; j < 4; j++) {
            float lo, hi; unpack2(A[cl][j], lo, hi);
            lo += bv; hi += bv;
            lo = lo > 0.f ? lo : av * lo;
            hi = hi > 0.f ? hi : av * hi;
            g_f2t[((b*CH2 + co)*Wn + (w_base + 2*j  ))*Hn + h] = lo;
            g_f2t[((b*CH2 + co)*Wn + (w_base + 2*j+1))*Hn + h] = hi;
        }
    }
}

// ---------------------------------------------------------------------------
// Fused: 1x1 conv (K=32) + softmax(9) + upsample. 128 threads.
// Thread = (c_l in 4, pq in 4, pg in 8): 9 logits x 8 h-pixels as f32x2.
// out[b][c][2w+q][2h+p] per reference transpose(0,1,5,3,4,2).
// ---------------------------------------------------------------------------
__global__ __launch_bounds__(128) void fused_kernel(
    const float* __restrict__ xlow, const float* __restrict__ kw,
    const float* __restrict__ kb, float* __restrict__ out)
{
    const int cchunk = blockIdx.x;   // 0..15 -> 4 channels
    const int w      = blockIdx.y;
    const int b      = blockIdx.z;
    const int tid = threadIdx.x;
    const int pg  = tid & 7;         // h = pg*8 + j
    const int pq  = (tid >> 3) & 3;
    const int c_l = tid >> 5;        // uniform per warp

    __shared__ ull swt[144*33];                    // duplicated weights, pad 33
    __shared__ __align__(16) float sf2[32*64];     // [ci][h]
    __shared__ float sx[4][3][66];                 // edge-clamped x_low patch
    __shared__ float sbias[144];

    for (int idx = tid; idx < 32*64; idx += 128)
        sf2[idx] = g_f2t[((b*CH2 + (idx >> 6))*Wn + w)*Hn + (idx & 63)];
    for (int idx = tid; idx < 144*32; idx += 128) {
        int r = idx >> 5, ci = idx & 31;
        float v = kw[(cchunk*144 + r)*32 + ci];
        swt[r*33 + ci] = pack2(v, v);
    }
    for (int idx = tid; idx < 144; idx += 128) sbias[idx] = kb[cchunk*144 + idx];
    for (int idx = tid; idx < 4*3*66; idx += 128) {
        int cl = idx / 198;
        int dx = (idx % 198) / 66;
        int hh = idx % 66;
        int hr = min(max(hh - 1, 0), Hn - 1);
        int wc = min(max(w + dx - 1, 0), Wn - 1);
        sx[cl][dx][hh] = xlow[((b*Cn + cchunk*4 + cl)*Hn + hr)*Wn + wc];
    }
    __syncthreads();

    ull m[9][4];
#pragma unroll
    for (int k = 0; k < 9; k++)
#pragma unroll
        for (int j = 0; j < 4; j++) m[k][j] = 0ull;

    const int rowbase = c_l*36 + pq;
#pragma unroll 2
    for (int ci = 0; ci < 32; ci++) {
        const float4 f0 = *(const float4*)(&sf2[ci*64 + pg*8]);
        const float4 f1 = *(const float4*)(&sf2[ci*64 + pg*8 + 4]);
        ull p0 = pack2(f0.x, f0.y);
        ull p1 = pack2(f0.z, f0.w);
        ull p2 = pack2(f1.x, f1.y);
        ull p3 = pack2(f1.z, f1.w);
#pragma unroll
        for (int k = 0; k < 9; k++) {
            ull a = swt[(rowbase + k*4)*33 + ci];
            m[k][0] = ffma2(a, p0, m[k][0]);
            m[k][1] = ffma2(a, p1, m[k][1]);
            m[k][2] = ffma2(a, p2, m[k][2]);
            m[k][3] = ffma2(a, p3, m[k][3]);
        }
    }

    float b9[9];
#pragma unroll
    for (int k = 0; k < 9; k++) b9[k] = sbias[rowbase + k*4];

    const int c = cchunk*4 + c_l;
    const int p = pq >> 1, q = pq & 1;
    float* orow = &out[((b*Cn + c)*128 + (2*w + q))*128 + p];

#pragma unroll
    for (int jj = 0; jj < 4; jj++) {
        float va[9], vb[9];
#pragma unroll
        for (int k = 0; k < 9; k++) unpack2(m[k][jj], va[k], vb[k]);

#pragma unroll
        for (int e = 0; e < 2; e++) {
            const int hpix = pg*8 + 2*jj + e;
            const float* lv = e ? vb : va;
            float lg[9];
            float mx = -1e30f;
#pragma unroll
            for (int k = 0; k < 9; k++) { lg[k] = lv[k] + b9[k]; mx = fmaxf(mx, lg[k]); }
            float se = 0.f, sv = 0.f;
#pragma unroll
            for (int k = 0; k < 9; k++) {
                float ex = __expf(lg[k] - mx);
                se += ex;
                float nb = sx[c_l][k % 3][hpix + (k / 3)];
                sv = fmaf(ex, nb, sv);
            }
            orow[2*hpix] = sv / se;
        }
    }
}

extern "C" void kernel_launch(void* const* d_in, const int* in_sizes, int n_in,
                              void* d_out, int out_size)
{
    const float* x_low = (const float*)d_in[0];
    const float* ctx   = (const float*)d_in[1];
    const float* c1_w  = (const float*)d_in[2];
    const float* c1_b  = (const float*)d_in[3];
    const float* p1_a  = (const float*)d_in[4];
    const float* c2_w  = (const float*)d_in[5];
    const float* c2_b  = (const float*)d_in[6];
    const float* p2_a  = (const float*)d_in[7];
    const float* kp_w  = (const float*)d_in[8];
    const float* kp_b  = (const float*)d_in[9];
    float* out = (float*)d_out;

    conv1_kernel<<<dim3(Hn/2, Bn), 256>>>(ctx, c1_w, c1_b, p1_a);
    conv2_kernel<<<dim3(Hn/2, Bn), 256>>>(c2_w, c2_b, p2_a);
    fused_kernel<<<dim3(16, Wn, Bn), 128>>>(x_low, kp_w, kp_b, out);
}